// round 2
// baseline (speedup 1.0000x reference)
#include <cuda_runtime.h>
#include <math.h>

// Problem constants
#define Bn 512   // batch
#define Nn 512   // nodes / input dim / hidden state size
#define Hn 256   // hidden_dim (message)

// Scratch (no cudaMalloc allowed)
__device__ float g_m[Bn * Hn];          // relu message   [512,256]
__device__ float g_gh[Bn * 3 * Nn];     // x@W_hh^T + b   [512,1536]

// ---------------------------------------------------------------------------
// Kernel 1 (heterogeneous):
//   blocks [0, 192):   gh GEMM  gh[b,j] = dot(x[b,:], W_hh[j,:]) + b_hh[j]
//                      tiles 64x64, BK=16, 256 thr, 4x4 per-thread microtile
//   blocks [192, 704): per-batch agg + fused message MLP
// ---------------------------------------------------------------------------
#define GH_BLOCKS 192   // (512/64) * (1536/64) = 8*24
#define AGG_BLOCKS Bn

__global__ __launch_bounds__(256, 4)
void k1_agg_m_gh(const float* __restrict__ x,
                 const float* __restrict__ adj,
                 const float* __restrict__ W_msg,
                 const float* __restrict__ b_msg,
                 const float* __restrict__ W_hh,
                 const float* __restrict__ b_hh)
{
    const int t = threadIdx.x;

    if (blockIdx.x < GH_BLOCKS) {
        // ---------------- gh GEMM: C[512,1536] = x[512,512] @ W_hh[1536,512]^T + b_hh
        __shared__ float As[16][68];   // [k][m], pad 68
        __shared__ float Bs[16][68];   // [k][n]

        const int gid = blockIdx.x;
        const int bn = gid % 24;       // n tile
        const int bm = gid / 24;       // m tile
        const int m0 = bm * 64;
        const int n0 = bn * 64;

        const int ldr = t >> 2;        // 0..63 row within tile
        const int kg  = (t & 3) * 4;   // k-subgroup start (0,4,8,12)

        const int ty = t >> 4;         // 0..15 -> output rows ty*4..
        const int tx = t & 15;         // 0..15 -> output cols tx*4..

        float acc[4][4];
#pragma unroll
        for (int i = 0; i < 4; i++)
#pragma unroll
            for (int j = 0; j < 4; j++) acc[i][j] = 0.f;

        for (int k0 = 0; k0 < Nn; k0 += 16) {
            float4 a = *(const float4*)&x[(m0 + ldr) * Nn + k0 + kg];
            float4 b = *(const float4*)&W_hh[(n0 + ldr) * Nn + k0 + kg];
            __syncthreads();
            As[kg + 0][ldr] = a.x; As[kg + 1][ldr] = a.y;
            As[kg + 2][ldr] = a.z; As[kg + 3][ldr] = a.w;
            Bs[kg + 0][ldr] = b.x; Bs[kg + 1][ldr] = b.y;
            Bs[kg + 2][ldr] = b.z; Bs[kg + 3][ldr] = b.w;
            __syncthreads();
#pragma unroll
            for (int kk = 0; kk < 16; kk++) {
                float ra[4], rb[4];
                *(float4*)ra = *(const float4*)&As[kk][ty * 4];
                *(float4*)rb = *(const float4*)&Bs[kk][tx * 4];
#pragma unroll
                for (int i = 0; i < 4; i++)
#pragma unroll
                    for (int j = 0; j < 4; j++)
                        acc[i][j] += ra[i] * rb[j];
            }
        }
#pragma unroll
        for (int i = 0; i < 4; i++) {
            const int row = m0 + ty * 4 + i;
#pragma unroll
            for (int j = 0; j < 4; j++) {
                const int col = n0 + tx * 4 + j;
                g_gh[row * (3 * Nn) + col] = acc[i][j] + b_hh[col];
            }
        }
    } else {
        // ---------------- agg + message for one batch row
        __shared__ float xs[Nn];
        __shared__ float aggs[Nn];

        const int b = blockIdx.x - GH_BLOCKS;
        xs[t]       = x[b * Nn + t];
        xs[t + 256] = x[b * Nn + 256 + t];
        __syncthreads();

        const int warp = t >> 5;
        const int lane = t & 31;
        const float4* adjb = (const float4*)(adj + (size_t)b * Nn * Nn);

#pragma unroll 2
        for (int r = warp; r < Nn; r += 8) {
            const float4* row = adjb + r * (Nn / 4);
            float acc = 0.f;
#pragma unroll
            for (int i = 0; i < 4; i++) {
                float4 a = row[lane + i * 32];
                const float* xp = &xs[(lane + i * 32) * 4];
                acc += a.x * xp[0] + a.y * xp[1] + a.z * xp[2] + a.w * xp[3];
            }
#pragma unroll
            for (int off = 16; off > 0; off >>= 1)
                acc += __shfl_down_sync(0xFFFFFFFFu, acc, off);
            if (lane == 0) aggs[r] = acc;
        }
        __syncthreads();

        // m[b][t] = relu(dot(aggs, W_msg[t,:]) + b_msg[t]),  t in [0,256)
        float acc = b_msg[t];
        const float4* wr = (const float4*)(W_msg + t * Nn);
#pragma unroll 8
        for (int k4 = 0; k4 < Nn / 4; k4++) {
            float4 w = wr[k4];
            const float* ap = &aggs[k4 * 4];
            acc += w.x * ap[0] + w.y * ap[1] + w.z * ap[2] + w.w * ap[3];
        }
        g_m[b * Hn + t] = fmaxf(acc, 0.f);
    }
}

// ---------------------------------------------------------------------------
// Kernel 2: gi GEMM (K=256) for the three gate sections + gate math + output
//   tiles: 32 (batch) x 64 (n) x K16, 128 threads, 4x4 microtile, 3 acc sets
// ---------------------------------------------------------------------------
__global__ __launch_bounds__(128, 4)
void k2_gates(const float* __restrict__ x,
              const float* __restrict__ W_ih,
              const float* __restrict__ b_ih,
              float* __restrict__ out)
{
    __shared__ float As[16][36];    // m tile   [k][row]
    __shared__ float Br[16][68];    // W_ih rows n0..        (r gate)
    __shared__ float Bz[16][68];    // W_ih rows 512+n0..    (z gate)
    __shared__ float Bq[16][68];    // W_ih rows 1024+n0..   (n gate)

    const int t  = threadIdx.x;
    const int bm = blockIdx.x >> 3;     // 0..15  (16 m tiles of 32)
    const int bn = blockIdx.x & 7;      // 0..7   (8 n tiles of 64)
    const int m0 = bm * 32;
    const int n0 = bn * 64;

    const int ldrA = t >> 2;            // 0..31
    const int kg   = (t & 3) * 4;
    const int ldrB = t >> 2;            // 0..31, +32 second pass

    const int ty = t >> 4;              // 0..7  -> rows ty*4..
    const int tx = t & 15;              // 0..15 -> cols tx*4..

    float aR[4][4], aZ[4][4], aQ[4][4];
#pragma unroll
    for (int i = 0; i < 4; i++)
#pragma unroll
        for (int j = 0; j < 4; j++) { aR[i][j] = 0.f; aZ[i][j] = 0.f; aQ[i][j] = 0.f; }

    for (int k0 = 0; k0 < Hn; k0 += 16) {
        float4 a = *(const float4*)&g_m[(m0 + ldrA) * Hn + k0 + kg];
        float4 r0 = *(const float4*)&W_ih[(n0 + ldrB) * Hn + k0 + kg];
        float4 r1 = *(const float4*)&W_ih[(n0 + ldrB + 32) * Hn + k0 + kg];
        float4 z0 = *(const float4*)&W_ih[(Nn + n0 + ldrB) * Hn + k0 + kg];
        float4 z1 = *(const float4*)&W_ih[(Nn + n0 + ldrB + 32) * Hn + k0 + kg];
        float4 q0 = *(const float4*)&W_ih[(2 * Nn + n0 + ldrB) * Hn + k0 + kg];
        float4 q1 = *(const float4*)&W_ih[(2 * Nn + n0 + ldrB + 32) * Hn + k0 + kg];
        __syncthreads();
        As[kg + 0][ldrA] = a.x; As[kg + 1][ldrA] = a.y;
        As[kg + 2][ldrA] = a.z; As[kg + 3][ldrA] = a.w;
        Br[kg + 0][ldrB] = r0.x; Br[kg + 1][ldrB] = r0.y; Br[kg + 2][ldrB] = r0.z; Br[kg + 3][ldrB] = r0.w;
        Br[kg + 0][ldrB + 32] = r1.x; Br[kg + 1][ldrB + 32] = r1.y; Br[kg + 2][ldrB + 32] = r1.z; Br[kg + 3][ldrB + 32] = r1.w;
        Bz[kg + 0][ldrB] = z0.x; Bz[kg + 1][ldrB] = z0.y; Bz[kg + 2][ldrB] = z0.z; Bz[kg + 3][ldrB] = z0.w;
        Bz[kg + 0][ldrB + 32] = z1.x; Bz[kg + 1][ldrB + 32] = z1.y; Bz[kg + 2][ldrB + 32] = z1.z; Bz[kg + 3][ldrB + 32] = z1.w;
        Bq[kg + 0][ldrB] = q0.x; Bq[kg + 1][ldrB] = q0.y; Bq[kg + 2][ldrB] = q0.z; Bq[kg + 3][ldrB] = q0.w;
        Bq[kg + 0][ldrB + 32] = q1.x; Bq[kg + 1][ldrB + 32] = q1.y; Bq[kg + 2][ldrB + 32] = q1.z; Bq[kg + 3][ldrB + 32] = q1.w;
        __syncthreads();
#pragma unroll
        for (int kk = 0; kk < 16; kk++) {
            float ra[4], rr[4], rz[4], rq[4];
#pragma unroll
            for (int i = 0; i < 4; i++) ra[i] = As[kk][ty * 4 + i];
            *(float4*)rr = *(const float4*)&Br[kk][tx * 4];
            *(float4*)rz = *(const float4*)&Bz[kk][tx * 4];
            *(float4*)rq = *(const float4*)&Bq[kk][tx * 4];
#pragma unroll
            for (int i = 0; i < 4; i++)
#pragma unroll
                for (int j = 0; j < 4; j++) {
                    aR[i][j] += ra[i] * rr[j];
                    aZ[i][j] += ra[i] * rz[j];
                    aQ[i][j] += ra[i] * rq[j];
                }
        }
    }

#pragma unroll
    for (int i = 0; i < 4; i++) {
        const int row = m0 + ty * 4 + i;
#pragma unroll
        for (int j = 0; j < 4; j++) {
            const int col = n0 + tx * 4 + j;
            const float i_r = aR[i][j] + b_ih[col];
            const float i_z = aZ[i][j] + b_ih[Nn + col];
            const float i_n = aQ[i][j] + b_ih[2 * Nn + col];
            const float h_r = g_gh[row * (3 * Nn) + col];
            const float h_z = g_gh[row * (3 * Nn) + Nn + col];
            const float h_n = g_gh[row * (3 * Nn) + 2 * Nn + col];
            const float r = 1.f / (1.f + expf(-(i_r + h_r)));
            const float z = 1.f / (1.f + expf(-(i_z + h_z)));
            const float nn = tanhf(i_n + r * h_n);
            const float xv = x[row * Nn + col];
            out[row * Nn + col] = (1.f - z) * nn + z * xv;
        }
    }
}

extern "C" void kernel_launch(void* const* d_in, const int* in_sizes, int n_in,
                              void* d_out, int out_size)
{
    (void)in_sizes; (void)n_in; (void)out_size;
    const float* x     = (const float*)d_in[0];
    const float* adj   = (const float*)d_in[1];
    const float* W_msg = (const float*)d_in[2];
    const float* b_msg = (const float*)d_in[3];
    const float* W_ih  = (const float*)d_in[4];
    const float* b_ih  = (const float*)d_in[5];
    const float* W_hh  = (const float*)d_in[6];
    const float* b_hh  = (const float*)d_in[7];
    float* out = (float*)d_out;

    k1_agg_m_gh<<<GH_BLOCKS + AGG_BLOCKS, 256>>>(x, adj, W_msg, b_msg, W_hh, b_hh);
    k2_gates<<<128, 128>>>(x, W_ih, b_ih, out);
}